// round 4
// baseline (speedup 1.0000x reference)
#include <cuda_runtime.h>
#include <cstdint>

#define TASKS  128
#define NSAMP  2048
#define INDIM  256
#define OUTDIM 256
#define TILE   16
#define XPAD   20      // 16 samples + 4 pad; row = 80B (16B-aligned)
#define MAXGRID 512

__device__ unsigned short g_slist[NSAMP];
__device__ int g_soff[TASKS + 1];
__device__ int g_twoff[TASKS + 1];

__device__ __forceinline__ unsigned smem_u32(const void* p) {
    unsigned r;
    asm("{ .reg .u64 t; cvta.to.shared.u64 t, %1; cvt.u32.u64 %0, t; }" : "=r"(r) : "l"(p));
    return r;
}

// ---------------- K1: build per-task sample lists + tile worklist prefix ----------------
__global__ __launch_bounds__(256) void k1_scan(const void* __restrict__ TIDS)
{
    __shared__ int cnts[TASKS];
    __shared__ int cursor[TASKS];
    __shared__ int soff[TASKS + 1];
    __shared__ int twoff[TASKS + 1];
    __shared__ int scan_tmp[TASKS];
    __shared__ unsigned orv;

    const int tid = threadIdx.x;
    if (tid < TASKS) { cnts[tid] = 0; cursor[tid] = 0; }
    if (tid == 0) orv = 0;
    __syncthreads();

    const unsigned* w32 = (const unsigned*)TIDS;
    atomicOr(&orv, w32[4 * tid + 1] | w32[4 * tid + 3]);
    __syncthreads();
    const int shift = (orv == 0) ? 1 : 0;

    int myid[8];
    #pragma unroll
    for (int j = 0; j < 8; ++j) {
        const int n = tid + 256 * j;
        myid[j] = (int)w32[(unsigned)n << shift];
        atomicAdd(&cnts[myid[j]], 1);
    }
    __syncthreads();

    if (tid < TASKS) scan_tmp[tid] = cnts[tid];
    __syncthreads();
    #pragma unroll
    for (int d = 1; d < TASKS; d <<= 1) {
        int v = 0;
        if (tid < TASKS && tid >= d) v = scan_tmp[tid - d];
        __syncthreads();
        if (tid < TASKS) scan_tmp[tid] += v;
        __syncthreads();
    }
    if (tid < TASKS) soff[tid + 1] = scan_tmp[tid];
    if (tid == 0) soff[0] = 0;
    __syncthreads();

    if (tid < TASKS) scan_tmp[tid] = (cnts[tid] + TILE - 1) / TILE;
    __syncthreads();
    #pragma unroll
    for (int d = 1; d < TASKS; d <<= 1) {
        int v = 0;
        if (tid < TASKS && tid >= d) v = scan_tmp[tid - d];
        __syncthreads();
        if (tid < TASKS) scan_tmp[tid] += v;
        __syncthreads();
    }
    if (tid < TASKS) twoff[tid + 1] = scan_tmp[tid];
    if (tid == 0) twoff[0] = 0;
    __syncthreads();

    #pragma unroll
    for (int j = 0; j < 8; ++j) {
        const int n = tid + 256 * j;
        const int t = myid[j];
        const int p = atomicAdd(&cursor[t], 1);
        g_slist[soff[t] + p] = (unsigned short)n;
    }
    if (tid <= TASKS) { g_soff[tid] = soff[tid]; g_twoff[tid] = twoff[tid]; }
}

// ---------------- K2 compute: static-register double-buffered f32x2 loop ----------------
// One "group" = 8 i-values. Dup W into f32x2 regs, issue prefetch LDGs for
// group buse+4, then run the LDS+FFMA2 stream. Array passed BY REFERENCE with
// static identity -> stays in registers (no runtime pointer selection!).
template<int PAIRS>
__device__ __forceinline__ void wgroup(float (&warr)[8],
                                       unsigned long long (&acc)[PAIRS],
                                       const float* __restrict__ Wt,
                                       unsigned xb, int buse)
{
    unsigned long long wd[8];
    #pragma unroll
    for (int j = 0; j < 8; ++j) {
        unsigned wu = __float_as_uint(warr[j]);
        asm("mov.b64 %0, {%1, %1};" : "=l"(wd[j]) : "r"(wu));
    }
    const int bl = buse + 4;
    if (bl < 32) {
        #pragma unroll
        for (int j = 0; j < 8; ++j)
            warr[j] = __ldg(Wt + (size_t)(bl * 8 + j) * OUTDIM);
    }
    #pragma unroll
    for (int j = 0; j < 8; ++j) {
        const unsigned addr = xb + (unsigned)(buse * 8 + j) * (XPAD * 4);
        if (PAIRS == 1) {
            unsigned long long a;
            asm("ld.shared.b64 %0, [%1];" : "=l"(a) : "r"(addr));
            asm("fma.rn.f32x2 %0, %1, %2, %0;" : "+l"(acc[0]) : "l"(a), "l"(wd[j]));
        } else {
            #pragma unroll
            for (int k2 = 0; k2 < PAIRS / 2; ++k2) {
                unsigned long long a, b2;
                asm("ld.shared.v2.b64 {%0, %1}, [%2];"
                    : "=l"(a), "=l"(b2) : "r"(addr + (unsigned)k2 * 16));
                asm("fma.rn.f32x2 %0, %1, %2, %0;" : "+l"(acc[2 * k2])     : "l"(a),  "l"(wd[j]));
                asm("fma.rn.f32x2 %0, %1, %2, %0;" : "+l"(acc[2 * k2 + 1]) : "l"(b2), "l"(wd[j]));
            }
        }
    }
}

template<int PAIRS>
__device__ __forceinline__ void compute_store(
    const float* __restrict__ Wt, float* __restrict__ OUT,
    const unsigned short* sl, unsigned xb, int scount, int o)
{
    unsigned long long acc[PAIRS];
    #pragma unroll
    for (int k = 0; k < PAIRS; ++k) acc[k] = 0ull;

    float w0[8], w1[8], w2[8], w3[8];
    #pragma unroll
    for (int j = 0; j < 8; ++j) {
        w0[j] = __ldg(Wt + (size_t)(0 * 8 + j) * OUTDIM);
        w1[j] = __ldg(Wt + (size_t)(1 * 8 + j) * OUTDIM);
        w2[j] = __ldg(Wt + (size_t)(2 * 8 + j) * OUTDIM);
        w3[j] = __ldg(Wt + (size_t)(3 * 8 + j) * OUTDIM);
    }

    #pragma unroll 1
    for (int bb = 0; bb < 8; ++bb) {
        const int b0 = bb * 4;
        wgroup<PAIRS>(w0, acc, Wt, xb, b0 + 0);
        wgroup<PAIRS>(w1, acc, Wt, xb, b0 + 1);
        wgroup<PAIRS>(w2, acc, Wt, xb, b0 + 2);
        wgroup<PAIRS>(w3, acc, Wt, xb, b0 + 3);
    }

    #pragma unroll
    for (int k = 0; k < PAIRS; ++k) {
        unsigned lo, hi;
        asm("mov.b64 {%0, %1}, %2;" : "=r"(lo), "=r"(hi) : "l"(acc[k]));
        const int s0 = 2 * k, s1 = s0 + 1;
        if (s0 < scount) OUT[(unsigned)sl[s0] * OUTDIM + o] = __uint_as_float(lo);
        if (s1 < scount) OUT[(unsigned)sl[s1] * OUTDIM + o] = __uint_as_float(hi);
    }
}

__global__ __launch_bounds__(128)
void k2_gemm(const float* __restrict__ X,
             const float* __restrict__ W,
             float* __restrict__ OUT)
{
    __shared__ __align__(16) float x_sm[INDIM * XPAD];
    __shared__ unsigned short sl[TILE];
    __shared__ int s_task, s_base, s_cnt;

    const int tid  = threadIdx.x;
    const int w    = blockIdx.x >> 1;
    const int half = blockIdx.x & 1;

    if (w >= g_twoff[TASKS]) return;

    if (tid < TASKS) {
        const int lo = g_twoff[tid], hi = g_twoff[tid + 1];
        if (lo <= w && w < hi) {
            const int so   = g_soff[tid];
            const int cntt = g_soff[tid + 1] - so;
            const int tile = w - lo;
            s_task = tid;
            s_base = so + tile * TILE;
            int sc = cntt - tile * TILE;
            s_cnt  = (sc > TILE) ? TILE : sc;
        }
    }
    __syncthreads();
    const int task = s_task, base = s_base, scount = s_cnt;

    if (tid < TILE) sl[tid] = (tid < scount) ? g_slist[base + tid] : (unsigned short)0;
    __syncthreads();

    // transposed tile load: thread -> (s = tid&15, q = tid>>4), 8 float4 rows each
    {
        const int s = tid & 15, q = tid >> 4;
        const bool valid = (s < scount);
        const float4* row = (const float4*)(X + (valid ? (unsigned)sl[s] * INDIM : 0u));
        #pragma unroll
        for (int k = 0; k < 8; ++k) {
            const int iv = q + 8 * k;
            float4 v;
            if (valid) v = __ldg(row + iv);
            else       v = make_float4(0.f, 0.f, 0.f, 0.f);
            const int i = iv * 4;
            x_sm[(i + 0) * XPAD + s] = v.x;
            x_sm[(i + 1) * XPAD + s] = v.y;
            x_sm[(i + 2) * XPAD + s] = v.z;
            x_sm[(i + 3) * XPAD + s] = v.w;
        }
    }
    __syncthreads();

    const int o = half * 128 + tid;
    const float* Wt = W + (size_t)task * INDIM * OUTDIM + o;
    const unsigned xb = smem_u32(x_sm);

    const int P = (scount > 8) ? 8 : (scount > 4) ? 4 : (scount > 2) ? 2 : 1;
    switch (P) {
        case 8:  compute_store<8>(Wt, OUT, sl, xb, scount, o); break;
        case 4:  compute_store<4>(Wt, OUT, sl, xb, scount, o); break;
        case 2:  compute_store<2>(Wt, OUT, sl, xb, scount, o); break;
        default: compute_store<1>(Wt, OUT, sl, xb, scount, o); break;
    }
}

extern "C" void kernel_launch(void* const* d_in, const int* in_sizes, int n_in,
                              void* d_out, int out_size)
{
    const float* X    = (const float*)d_in[0];
    const void*  TIDS = d_in[1];
    const float* W    = (const float*)d_in[2];
    float*       OUT  = (float*)d_out;

    k1_scan<<<1, 256>>>(TIDS);
    k2_gemm<<<MAXGRID, 128>>>(X, W, OUT);
}

// round 5
// speedup vs baseline: 1.0012x; 1.0012x over previous
#include <cuda_runtime.h>
#include <cstdint>

#define TASKS  128
#define NSAMP  2048
#define INDIM  256
#define OUTDIM 256
#define TILE   16
#define IHALF  128     // i-values per K-split CTA
#define NGROUP 16      // groups of 8 i-values per CTA
#define XPAD   20      // 16 samples + 4 pad; i-row stride 80B (16B aligned)
#define MAXGRID 1024   // 256 max tiles * 2 col-halves * 2 K-halves

__device__ unsigned short g_slist[NSAMP];
__device__ int g_soff[TASKS + 1];
__device__ int g_twoff[TASKS + 1];
__device__ float g_part[2][NSAMP][OUTDIM];   // K-split partials (static, 4MB)

__device__ __forceinline__ unsigned smem_u32(const void* p) {
    unsigned r;
    asm("{ .reg .u64 t; cvta.to.shared.u64 t, %1; cvt.u32.u64 %0, t; }" : "=r"(r) : "l"(p));
    return r;
}

// ---------------- K1: per-task sample lists + tile worklist prefix ----------------
__global__ __launch_bounds__(256) void k1_scan(const void* __restrict__ TIDS)
{
    __shared__ int cnts[TASKS];
    __shared__ int cursor[TASKS];
    __shared__ int soff[TASKS + 1];
    __shared__ int twoff[TASKS + 1];
    __shared__ int scan_tmp[TASKS];
    __shared__ unsigned orv;

    const int tid = threadIdx.x;
    if (tid < TASKS) { cnts[tid] = 0; cursor[tid] = 0; }
    if (tid == 0) orv = 0;
    __syncthreads();

    const unsigned* w32 = (const unsigned*)TIDS;
    atomicOr(&orv, w32[4 * tid + 1] | w32[4 * tid + 3]);
    __syncthreads();
    const int shift = (orv == 0) ? 1 : 0;

    int myid[8];
    #pragma unroll
    for (int j = 0; j < 8; ++j) {
        const int n = tid + 256 * j;
        myid[j] = (int)w32[(unsigned)n << shift];
        atomicAdd(&cnts[myid[j]], 1);
    }
    __syncthreads();

    if (tid < TASKS) scan_tmp[tid] = cnts[tid];
    __syncthreads();
    #pragma unroll
    for (int d = 1; d < TASKS; d <<= 1) {
        int v = 0;
        if (tid < TASKS && tid >= d) v = scan_tmp[tid - d];
        __syncthreads();
        if (tid < TASKS) scan_tmp[tid] += v;
        __syncthreads();
    }
    if (tid < TASKS) soff[tid + 1] = scan_tmp[tid];
    if (tid == 0) soff[0] = 0;
    __syncthreads();

    if (tid < TASKS) scan_tmp[tid] = (cnts[tid] + TILE - 1) / TILE;
    __syncthreads();
    #pragma unroll
    for (int d = 1; d < TASKS; d <<= 1) {
        int v = 0;
        if (tid < TASKS && tid >= d) v = scan_tmp[tid - d];
        __syncthreads();
        if (tid < TASKS) scan_tmp[tid] += v;
        __syncthreads();
    }
    if (tid < TASKS) twoff[tid + 1] = scan_tmp[tid];
    if (tid == 0) twoff[0] = 0;
    __syncthreads();

    #pragma unroll
    for (int j = 0; j < 8; ++j) {
        const int n = tid + 256 * j;
        const int t = myid[j];
        const int p = atomicAdd(&cursor[t], 1);
        g_slist[soff[t] + p] = (unsigned short)n;
    }
    if (tid <= TASKS) { g_soff[tid] = soff[tid]; g_twoff[tid] = twoff[tid]; }
}

// ---------------- K2 compute: batched-LDS f32x2 loop over one K-half ----------------
template<int PAIRS>
__device__ __forceinline__ void wgroup(float (&warr)[8],
                                       unsigned long long (&acc)[PAIRS],
                                       const float* __restrict__ Wt,
                                       unsigned xb, int buse)
{
    // Prefetch group buse+4 into this (now consumable) buffer after dup.
    unsigned long long wd[8];
    #pragma unroll
    for (int j = 0; j < 8; ++j) {
        unsigned wu = __float_as_uint(warr[j]);
        asm("mov.b64 %0, {%1, %1};" : "=l"(wd[j]) : "r"(wu));
    }
    const int bl = buse + 4;
    if (bl < NGROUP) {
        #pragma unroll
        for (int j = 0; j < 8; ++j)
            warr[j] = __ldg(Wt + (size_t)(bl * 8 + j) * OUTDIM);
    }
    #pragma unroll
    for (int j = 0; j < 8; ++j) {
        const unsigned addr = xb + (unsigned)(buse * 8 + j) * (XPAD * 4);
        if (PAIRS == 1) {
            unsigned long long a;
            asm("ld.shared.b64 %0, [%1];" : "=l"(a) : "r"(addr));
            asm("fma.rn.f32x2 %0, %1, %2, %0;" : "+l"(acc[0]) : "l"(a), "l"(wd[j]));
        } else if (PAIRS == 2) {
            unsigned long long a, b;
            asm("ld.shared.v2.b64 {%0, %1}, [%2];" : "=l"(a), "=l"(b) : "r"(addr));
            asm("fma.rn.f32x2 %0, %1, %2, %0;" : "+l"(acc[0]) : "l"(a), "l"(wd[j]));
            asm("fma.rn.f32x2 %0, %1, %2, %0;" : "+l"(acc[1]) : "l"(b), "l"(wd[j]));
        } else if (PAIRS == 4) {
            unsigned long long a, b, c, d;
            asm("ld.shared.v2.b64 {%0, %1}, [%2];" : "=l"(a), "=l"(b) : "r"(addr));
            asm("ld.shared.v2.b64 {%0, %1}, [%2];" : "=l"(c), "=l"(d) : "r"(addr + 16));
            asm("fma.rn.f32x2 %0, %1, %2, %0;" : "+l"(acc[0]) : "l"(a), "l"(wd[j]));
            asm("fma.rn.f32x2 %0, %1, %2, %0;" : "+l"(acc[1]) : "l"(b), "l"(wd[j]));
            asm("fma.rn.f32x2 %0, %1, %2, %0;" : "+l"(acc[2]) : "l"(c), "l"(wd[j]));
            asm("fma.rn.f32x2 %0, %1, %2, %0;" : "+l"(acc[3]) : "l"(d), "l"(wd[j]));
        } else {
            // PAIRS == 8: batch ALL four v2.b64 loads, then run the 8 FFMA2s.
            unsigned long long x0, x1, x2, x3, x4, x5, x6, x7;
            asm("ld.shared.v2.b64 {%0, %1}, [%2];" : "=l"(x0), "=l"(x1) : "r"(addr));
            asm("ld.shared.v2.b64 {%0, %1}, [%2];" : "=l"(x2), "=l"(x3) : "r"(addr + 16));
            asm("ld.shared.v2.b64 {%0, %1}, [%2];" : "=l"(x4), "=l"(x5) : "r"(addr + 32));
            asm("ld.shared.v2.b64 {%0, %1}, [%2];" : "=l"(x6), "=l"(x7) : "r"(addr + 48));
            asm("fma.rn.f32x2 %0, %1, %2, %0;" : "+l"(acc[0]) : "l"(x0), "l"(wd[j]));
            asm("fma.rn.f32x2 %0, %1, %2, %0;" : "+l"(acc[1]) : "l"(x1), "l"(wd[j]));
            asm("fma.rn.f32x2 %0, %1, %2, %0;" : "+l"(acc[2]) : "l"(x2), "l"(wd[j]));
            asm("fma.rn.f32x2 %0, %1, %2, %0;" : "+l"(acc[3]) : "l"(x3), "l"(wd[j]));
            asm("fma.rn.f32x2 %0, %1, %2, %0;" : "+l"(acc[4]) : "l"(x4), "l"(wd[j]));
            asm("fma.rn.f32x2 %0, %1, %2, %0;" : "+l"(acc[5]) : "l"(x5), "l"(wd[j]));
            asm("fma.rn.f32x2 %0, %1, %2, %0;" : "+l"(acc[6]) : "l"(x6), "l"(wd[j]));
            asm("fma.rn.f32x2 %0, %1, %2, %0;" : "+l"(acc[7]) : "l"(x7), "l"(wd[j]));
        }
    }
}

template<int PAIRS>
__device__ __forceinline__ void compute_store(
    const float* __restrict__ Wt, float* __restrict__ P,
    const unsigned short* sl, unsigned xb, int scount, int o)
{
    unsigned long long acc[PAIRS];
    #pragma unroll
    for (int k = 0; k < PAIRS; ++k) acc[k] = 0ull;

    float w0[8], w1[8], w2[8], w3[8];
    #pragma unroll
    for (int j = 0; j < 8; ++j) {
        w0[j] = __ldg(Wt + (size_t)(0 * 8 + j) * OUTDIM);
        w1[j] = __ldg(Wt + (size_t)(1 * 8 + j) * OUTDIM);
        w2[j] = __ldg(Wt + (size_t)(2 * 8 + j) * OUTDIM);
        w3[j] = __ldg(Wt + (size_t)(3 * 8 + j) * OUTDIM);
    }

    #pragma unroll 1
    for (int bb = 0; bb < NGROUP / 4; ++bb) {
        const int b0 = bb * 4;
        wgroup<PAIRS>(w0, acc, Wt, xb, b0 + 0);
        wgroup<PAIRS>(w1, acc, Wt, xb, b0 + 1);
        wgroup<PAIRS>(w2, acc, Wt, xb, b0 + 2);
        wgroup<PAIRS>(w3, acc, Wt, xb, b0 + 3);
    }

    #pragma unroll
    for (int k = 0; k < PAIRS; ++k) {
        unsigned lo, hi;
        asm("mov.b64 {%0, %1}, %2;" : "=r"(lo), "=r"(hi) : "l"(acc[k]));
        const int s0 = 2 * k, s1 = s0 + 1;
        if (s0 < scount) P[(unsigned)sl[s0] * OUTDIM + o] = __uint_as_float(lo);
        if (s1 < scount) P[(unsigned)sl[s1] * OUTDIM + o] = __uint_as_float(hi);
    }
}

__global__ __launch_bounds__(128)
void k2_gemm(const float* __restrict__ X,
             const float* __restrict__ W)
{
    __shared__ __align__(16) float x_sm[IHALF * XPAD];
    __shared__ unsigned short sl[TILE];
    __shared__ int s_task, s_base, s_cnt;

    const int tid  = threadIdx.x;
    const int w    = blockIdx.x >> 2;      // tile id
    const int sub  = blockIdx.x & 3;
    const int half = sub & 1;              // output-column half
    const int kh   = sub >> 1;             // K half

    if (w >= g_twoff[TASKS]) return;

    if (tid < TASKS) {
        const int lo = g_twoff[tid], hi = g_twoff[tid + 1];
        if (lo <= w && w < hi) {
            const int so   = g_soff[tid];
            const int cntt = g_soff[tid + 1] - so;
            const int tile = w - lo;
            s_task = tid;
            s_base = so + tile * TILE;
            int sc = cntt - tile * TILE;
            s_cnt  = (sc > TILE) ? TILE : sc;
        }
    }
    __syncthreads();
    const int task = s_task, base = s_base, scount = s_cnt;

    if (tid < TILE) sl[tid] = (tid < scount) ? g_slist[base + tid] : (unsigned short)0;
    __syncthreads();

    // transposed half-tile load: 16 samples x 128 i-values (this K half)
    {
        const int s = tid & 15, q = tid >> 4;   // q: 0..7
        const bool valid = (s < scount);
        const float4* row = (const float4*)(X + (valid ? (unsigned)sl[s] * INDIM : 0u)
                                              + kh * IHALF);
        #pragma unroll
        for (int k = 0; k < 4; ++k) {
            const int iv = q + 8 * k;           // 0..31
            float4 v;
            if (valid) v = __ldg(row + iv);
            else       v = make_float4(0.f, 0.f, 0.f, 0.f);
            const int i = iv * 4;
            x_sm[(i + 0) * XPAD + s] = v.x;
            x_sm[(i + 1) * XPAD + s] = v.y;
            x_sm[(i + 2) * XPAD + s] = v.z;
            x_sm[(i + 3) * XPAD + s] = v.w;
        }
    }
    __syncthreads();

    const int o = half * 128 + tid;
    const float* Wt = W + (size_t)task * INDIM * OUTDIM + (size_t)(kh * IHALF) * OUTDIM + o;
    float* P = &g_part[kh][0][0];
    const unsigned xb = smem_u32(x_sm);

    const int Pn = (scount > 8) ? 8 : (scount > 4) ? 4 : (scount > 2) ? 2 : 1;
    switch (Pn) {
        case 8:  compute_store<8>(Wt, P, sl, xb, scount, o); break;
        case 4:  compute_store<4>(Wt, P, sl, xb, scount, o); break;
        case 2:  compute_store<2>(Wt, P, sl, xb, scount, o); break;
        default: compute_store<1>(Wt, P, sl, xb, scount, o); break;
    }
}

// ---------------- K3: sum the two K-half partials ----------------
__global__ __launch_bounds__(256) void k3_reduce(float* __restrict__ OUT)
{
    const int idx = blockIdx.x * 256 + threadIdx.x;   // float4 index
    const float4* p0 = (const float4*)&g_part[0][0][0];
    const float4* p1 = (const float4*)&g_part[1][0][0];
    float4 a = p0[idx], b = p1[idx];
    float4 r = make_float4(a.x + b.x, a.y + b.y, a.z + b.z, a.w + b.w);
    ((float4*)OUT)[idx] = r;
}

extern "C" void kernel_launch(void* const* d_in, const int* in_sizes, int n_in,
                              void* d_out, int out_size)
{
    const float* X    = (const float*)d_in[0];
    const void*  TIDS = d_in[1];
    const float* W    = (const float*)d_in[2];
    float*       OUT  = (float*)d_out;

    k1_scan<<<1, 256>>>(TIDS);
    k2_gemm<<<MAXGRID, 128>>>(X, W);
    k3_reduce<<<(NSAMP * OUTDIM / 4) / 256, 256>>>(OUT);
}